// round 4
// baseline (speedup 1.0000x reference)
#include <cuda_runtime.h>
#include <math.h>

#define Bx  4
#define Tx  2048
#define Dx  768
#define Hx  12
#define HDx 64
#define Mx  (Bx*Tx)   // 8192

// Scratch (allocation-free rule: __device__ globals)
__device__ float g_q[Bx*Hx*Tx*HDx];
__device__ float g_k[Bx*Hx*Tx*HDx];
__device__ float g_v[Bx*Hx*Tx*HDx];
__device__ float g_ctx[Bx*Tx*Dx];

// ---------------------------------------------------------------------------
// SGEMM: C[M,N] = A[M,K] @ W[K,N]   (K = N = 768, M = 8192)
// 128x128 tile, BK=8, 256 threads, 8x8 micro-tile per thread.
// mode 0: scatter into [b,h,t,hd] layout (QKV).  mode 1: row-major + bias.
// ---------------------------------------------------------------------------
__global__ __launch_bounds__(256) void gemm128(const float* __restrict__ A,
                                               const float* __restrict__ W,
                                               float* __restrict__ dst,
                                               const float* __restrict__ bias,
                                               int mode)
{
    __shared__ float As[8][128];   // transposed: As[k][m]
    __shared__ float Bs[8][128];   // Bs[k][n]

    const int tid = threadIdx.x;
    const int m0  = blockIdx.y * 128;
    const int n0  = blockIdx.x * 128;
    const int tx  = tid & 15;       // 0..15  -> col group
    const int ty  = tid >> 4;       // 0..15  -> row group

    const int arow = tid >> 1;          // 0..127
    const int aseg = (tid & 1) << 2;    // 0 or 4
    const int brow = tid >> 5;          // 0..7
    const int bcol = (tid & 31) << 2;   // 0..124

    float c[8][8];
#pragma unroll
    for (int i = 0; i < 8; i++)
#pragma unroll
        for (int j = 0; j < 8; j++) c[i][j] = 0.f;

    const float* aptr = A + (size_t)(m0 + arow) * Dx + aseg;
    const float* bptr = W + (size_t)brow * Dx + n0 + bcol;

    for (int k0 = 0; k0 < Dx; k0 += 8) {
        float4 av = *(const float4*)(aptr + k0);
        float4 bv = *(const float4*)(bptr + (size_t)k0 * Dx);

        As[aseg + 0][arow] = av.x;
        As[aseg + 1][arow] = av.y;
        As[aseg + 2][arow] = av.z;
        As[aseg + 3][arow] = av.w;
        *(float4*)&Bs[brow][bcol] = bv;
        __syncthreads();

#pragma unroll
        for (int kk = 0; kk < 8; kk++) {
            float a[8], b[8];
            *(float4*)(a)     = *(const float4*)&As[kk][ty * 8];
            *(float4*)(a + 4) = *(const float4*)&As[kk][ty * 8 + 4];
            *(float4*)(b)     = *(const float4*)&Bs[kk][tx * 8];
            *(float4*)(b + 4) = *(const float4*)&Bs[kk][tx * 8 + 4];
#pragma unroll
            for (int i = 0; i < 8; i++)
#pragma unroll
                for (int j = 0; j < 8; j++)
                    c[i][j] += a[i] * b[j];
        }
        __syncthreads();
    }

    if (mode == 0) {
#pragma unroll
        for (int i = 0; i < 8; i++) {
            int m = m0 + ty * 8 + i;
            int bb = m / Tx, t = m % Tx;
#pragma unroll
            for (int j = 0; j < 8; j++) {
                int n = n0 + tx * 8 + j;
                int h = n / HDx, hd = n % HDx;
                dst[(((size_t)bb * Hx + h) * Tx + t) * HDx + hd] = c[i][j];
            }
        }
    } else {
#pragma unroll
        for (int i = 0; i < 8; i++) {
            int m = m0 + ty * 8 + i;
#pragma unroll
            for (int j = 0; j < 8; j++) {
                int n = n0 + tx * 8 + j;
                dst[(size_t)m * Dx + n] = c[i][j] + bias[n];
            }
        }
    }
}

// ---------------------------------------------------------------------------
// Causal flash attention, fp32. One CTA per (64-row q tile, b*h).
// 256 threads; thread (trow,tcol) owns a 4x4 micro-tile of both S and O.
// ---------------------------------------------------------------------------
__global__ __launch_bounds__(256) void attn64(const float* __restrict__ gq,
                                              const float* __restrict__ gk,
                                              const float* __restrict__ gv,
                                              float* __restrict__ gctx)
{
    extern __shared__ float sm[];
    float (*Qs)[65] = (float(*)[65])(sm);
    float (*Ks)[65] = (float(*)[65])(sm + 64 * 65);
    float (*Vs)[65] = (float(*)[65])(sm + 2 * 64 * 65);
    float (*Ps)[65] = (float(*)[65])(sm + 3 * 64 * 65);

    const int tid = threadIdx.x;
    const int bh  = blockIdx.y;                    // 0..47
    const int qt  = gridDim.x - 1 - blockIdx.x;    // big tiles scheduled first
    const int q0  = qt * 64;
    const int bb  = bh / Hx, h = bh % Hx;

    const float* qb = gq + (size_t)bh * Tx * HDx;
    const float* kb = gk + (size_t)bh * Tx * HDx;
    const float* vb = gv + (size_t)bh * Tx * HDx;

    // Load Q tile (64x64 floats)
#pragma unroll
    for (int it = 0; it < 4; it++) {
        int idx = tid + it * 256;              // float4 index 0..1023
        int r   = idx >> 4;
        int c4  = (idx & 15) << 2;
        float4 vq = *(const float4*)&qb[(size_t)(q0 + r) * HDx + c4];
        Qs[r][c4] = vq.x; Qs[r][c4 + 1] = vq.y; Qs[r][c4 + 2] = vq.z; Qs[r][c4 + 3] = vq.w;
    }

    const int trow = tid >> 4;       // 0..15
    const int tcol = tid & 15;       // 0..15
    const int r0 = trow * 4;
    const int c0 = tcol * 4;

    float o[4][4];
    float mrow[4], lrow[4];
#pragma unroll
    for (int i = 0; i < 4; i++) {
        mrow[i] = -1e30f;
        lrow[i] = 0.f;
#pragma unroll
        for (int j = 0; j < 4; j++) o[i][j] = 0.f;
    }

    for (int kt = 0; kt <= qt; kt++) {
        __syncthreads();   // prior tile's P·V reads done; (covers Q store on iter 0)

        // Load K, V tiles for this kv block
#pragma unroll
        for (int it = 0; it < 4; it++) {
            int idx = tid + it * 256;
            int r   = idx >> 4;
            int c4  = (idx & 15) << 2;
            size_t off = (size_t)(kt * 64 + r) * HDx + c4;
            float4 kv = *(const float4*)&kb[off];
            Ks[r][c4] = kv.x; Ks[r][c4 + 1] = kv.y; Ks[r][c4 + 2] = kv.z; Ks[r][c4 + 3] = kv.w;
            float4 vv = *(const float4*)&vb[off];
            Vs[r][c4] = vv.x; Vs[r][c4 + 1] = vv.y; Vs[r][c4 + 2] = vv.z; Vs[r][c4 + 3] = vv.w;
        }
        __syncthreads();

        // S = Q K^T  (4x4 micro-tile)
        float s[4][4];
#pragma unroll
        for (int i = 0; i < 4; i++)
#pragma unroll
            for (int j = 0; j < 4; j++) s[i][j] = 0.f;

#pragma unroll 8
        for (int d = 0; d < 64; d++) {
            float qv[4], kv[4];
#pragma unroll
            for (int i = 0; i < 4; i++) qv[i] = Qs[r0 + i][d];
#pragma unroll
            for (int j = 0; j < 4; j++) kv[j] = Ks[c0 + j][d];
#pragma unroll
            for (int i = 0; i < 4; i++)
#pragma unroll
                for (int j = 0; j < 4; j++)
                    s[i][j] += qv[i] * kv[j];
        }

        // scale 1/sqrt(64) + causal mask (only diagonal tile needs masking)
#pragma unroll
        for (int i = 0; i < 4; i++)
#pragma unroll
            for (int j = 0; j < 4; j++)
                s[i][j] *= 0.125f;
        if (kt == qt) {
#pragma unroll
            for (int i = 0; i < 4; i++)
#pragma unroll
                for (int j = 0; j < 4; j++)
                    if (c0 + j > r0 + i) s[i][j] = -1e30f;
        }

        // Online softmax update (row group = 16 consecutive lanes)
#pragma unroll
        for (int i = 0; i < 4; i++) {
            float tm = fmaxf(fmaxf(s[i][0], s[i][1]), fmaxf(s[i][2], s[i][3]));
#pragma unroll
            for (int off = 8; off; off >>= 1)
                tm = fmaxf(tm, __shfl_xor_sync(0xffffffffu, tm, off));
            float mnew = fmaxf(mrow[i], tm);
            float corr = __expf(mrow[i] - mnew);
            float p[4];
            float rs = 0.f;
#pragma unroll
            for (int j = 0; j < 4; j++) { p[j] = __expf(s[i][j] - mnew); rs += p[j]; }
#pragma unroll
            for (int off = 8; off; off >>= 1)
                rs += __shfl_xor_sync(0xffffffffu, rs, off);
            lrow[i] = lrow[i] * corr + rs;
            mrow[i] = mnew;
#pragma unroll
            for (int j = 0; j < 4; j++) o[i][j] *= corr;
            Ps[r0 + i][c0 + 0] = p[0];
            Ps[r0 + i][c0 + 1] = p[1];
            Ps[r0 + i][c0 + 2] = p[2];
            Ps[r0 + i][c0 + 3] = p[3];
        }
        __syncthreads();

        // O += P V  (4x4 micro-tile over hd columns)
#pragma unroll 8
        for (int cc = 0; cc < 64; cc++) {
            float pv[4], vv[4];
#pragma unroll
            for (int i = 0; i < 4; i++) pv[i] = Ps[r0 + i][cc];
#pragma unroll
            for (int j = 0; j < 4; j++) vv[j] = Vs[cc][c0 + j];
#pragma unroll
            for (int i = 0; i < 4; i++)
#pragma unroll
                for (int j = 0; j < 4; j++)
                    o[i][j] += pv[i] * vv[j];
        }
    }

    // Normalize and write ctx in [b, t, h*HD] layout
#pragma unroll
    for (int i = 0; i < 4; i++) {
        float inv = 1.0f / lrow[i];
        int tglob = q0 + r0 + i;
        float* dst = gctx + ((size_t)bb * Tx + tglob) * Dx + h * HDx + c0;
        float4 w;
        w.x = o[i][0] * inv;
        w.y = o[i][1] * inv;
        w.z = o[i][2] * inv;
        w.w = o[i][3] * inv;
        *(float4*)dst = w;
    }
}

// ---------------------------------------------------------------------------
extern "C" void kernel_launch(void* const* d_in, const int* in_sizes, int n_in,
                              void* d_out, int out_size)
{
    (void)in_sizes; (void)n_in; (void)out_size;
    const float* x  = (const float*)d_in[0];
    const float* Wq = (const float*)d_in[1];
    const float* Wk = (const float*)d_in[2];
    const float* Wv = (const float*)d_in[3];
    const float* Wo = (const float*)d_in[4];
    const float* bo = (const float*)d_in[5];
    float* out = (float*)d_out;

    float *q, *k, *v, *ctx;
    cudaGetSymbolAddress((void**)&q,   g_q);
    cudaGetSymbolAddress((void**)&k,   g_k);
    cudaGetSymbolAddress((void**)&v,   g_v);
    cudaGetSymbolAddress((void**)&ctx, g_ctx);

    dim3 ggrid(Dx / 128, Mx / 128);   // (6, 64)

    gemm128<<<ggrid, 256>>>(x, Wq, q, nullptr, 0);
    gemm128<<<ggrid, 256>>>(x, Wk, k, nullptr, 0);
    gemm128<<<ggrid, 256>>>(x, Wv, v, nullptr, 0);

    const int smem = 4 * 64 * 65 * 4;   // 66560 B
    cudaFuncSetAttribute(attn64, cudaFuncAttributeMaxDynamicSharedMemorySize, smem);
    attn64<<<dim3(Tx / 64, Bx * Hx), 256, smem>>>(q, k, v, ctx);

    gemm128<<<ggrid, 256>>>(ctx, Wo, out, bo, 1);
}

// round 7
// speedup vs baseline: 1.4410x; 1.4410x over previous
#include <cuda_runtime.h>
#include <cuda_bf16.h>
#include <math.h>
#include <stdint.h>

#define Bx  4
#define Tx  2048
#define Dx  768
#define Hx  12
#define HDx 64
#define Mx  (Bx*Tx)   // 8192
#define WE  (Dx*Dx)   // 589824

typedef __nv_bfloat16 bf16;

// ---------------- scratch (allocation-free rule: __device__ globals) -------
__device__ float g_q[Bx*Hx*Tx*HDx];
__device__ float g_k[Bx*Hx*Tx*HDx];
__device__ float g_v[Bx*Hx*Tx*HDx];
__device__ float g_ctx[Bx*Tx*Dx];
__device__ bf16  g_xh[Mx*Dx], g_xl[Mx*Dx];
__device__ bf16  g_ch[Mx*Dx], g_cl[Mx*Dx];
__device__ bf16  g_wh[4*WE],  g_wl[4*WE];   // K-major transposed weights [N][K]

// ---------------- portable tensor-core helpers (sm_80+) --------------------
__device__ __forceinline__ uint32_t smem_u32(const void* p) {
    uint32_t a;
    asm("{ .reg .u64 t; cvta.to.shared.u64 t, %1; cvt.u32.u64 %0, t; }"
        : "=r"(a) : "l"(p));
    return a;
}
__device__ __forceinline__ void ldsm4(uint32_t* r, uint32_t addr) {
    asm volatile("ldmatrix.sync.aligned.m8n8.x4.shared.b16 {%0,%1,%2,%3}, [%4];"
                 : "=r"(r[0]), "=r"(r[1]), "=r"(r[2]), "=r"(r[3]) : "r"(addr));
}
__device__ __forceinline__ void mma16816(float* c, const uint32_t* a, const uint32_t* b) {
    asm volatile("mma.sync.aligned.m16n8k16.row.col.f32.bf16.bf16.f32 "
                 "{%0,%1,%2,%3}, {%4,%5,%6,%7}, {%8,%9}, {%0,%1,%2,%3};"
                 : "+f"(c[0]), "+f"(c[1]), "+f"(c[2]), "+f"(c[3])
                 : "r"(a[0]), "r"(a[1]), "r"(a[2]), "r"(a[3]),
                   "r"(b[0]), "r"(b[1]));
}

// ---------------------------------------------------------------------------
// Split-precision conversion kernels
// ---------------------------------------------------------------------------
__global__ void split_f32(const float* __restrict__ in,
                          bf16* __restrict__ hi, bf16* __restrict__ lo, int n) {
    int i = blockIdx.x * 256 + threadIdx.x;
    if (i < n) {
        float f = in[i];
        bf16 h = __float2bfloat16(f);
        hi[i] = h;
        lo[i] = __float2bfloat16(f - __bfloat162float(h));
    }
}
// W [K,N] fp32 -> K-major [N,K] bf16 hi/lo
__global__ void splitT_f32(const float* __restrict__ w,
                           bf16* __restrict__ hi, bf16* __restrict__ lo) {
    int i = blockIdx.x * 256 + threadIdx.x;   // i = n*Dx + k
    int n = i / Dx, k = i - n * Dx;
    float f = w[(size_t)k * Dx + n];
    bf16 h = __float2bfloat16(f);
    hi[i] = h;
    lo[i] = __float2bfloat16(f - __bfloat162float(h));
}

// ---------------------------------------------------------------------------
// HMMA bf16x3 GEMM: C[M,768] = A[M,768] @ B^T  (B stored [N,K] K-major)
// 128x128 CTA tile, BK=32, 8 warps (warp tile 32x64), single smem buffer
// with register-staged LDG prefetch.  mode 0: scatter [b,h,t,hd]; 1: +bias.
// ---------------------------------------------------------------------------
#define PAD_ELEM 40                  // 32 + 8 bf16  -> 80B row stride
#define ROWB     (PAD_ELEM*2)        // 80 bytes
#define TILE_B   (128*ROWB)          // 10240 bytes per tensor
#define SA_H 0
#define SA_L (TILE_B)
#define SB_H (2*TILE_B)
#define SB_L (3*TILE_B)
#define SM_GTOT (4*TILE_B)           // 40960 bytes

__global__ __launch_bounds__(256) void gemm_hmma(
    const bf16* __restrict__ Ah, const bf16* __restrict__ Al,
    const bf16* __restrict__ Bh, const bf16* __restrict__ Bl,
    float* __restrict__ dst, const float* __restrict__ bias, int mode)
{
    extern __shared__ char smem[];
    const uint32_t sb = smem_u32(smem);
    const int tid = threadIdx.x, wid = tid >> 5, lane = tid & 31;
    const int m0 = blockIdx.y * 128, n0 = blockIdx.x * 128;

    const int warp_m = (wid & 3) * 32;       // 0,32,64,96
    const int warp_n = (wid >> 2) * 64;      // 0,64

    // ---- ldmatrix lane address offsets (within tile, bytes) ----
    // A (row-major 16x16 frags): lanes 0-15 rows, lanes 16-31 rows @ col+8
    const uint32_t a_lrow = (uint32_t)(lane & 15);
    const uint32_t a_lcol = (uint32_t)(lane >> 4) * 16u;   // bytes
    // B ([N][K] frags): g0: n+l,k ; g1: n+l,k+8 ; g2: n+8+l,k ; g3: n+8+l,k+8
    const uint32_t b_l = (uint32_t)(lane & 7), b_g = (uint32_t)(lane >> 3);
    const uint32_t b_nrow = ((b_g >> 1) << 3) + b_l;
    const uint32_t b_koff = (b_g & 1) << 4;                // bytes

    // ---- global load mapping: 512 uint4 per tensor per stage ----
    // idx = tid + i*256 ; row = idx>>2 ; chunk = (idx&3)*8 elems
    float acc[2][8][4];
#pragma unroll
    for (int mi = 0; mi < 2; mi++)
#pragma unroll
        for (int ni = 0; ni < 8; ni++)
#pragma unroll
            for (int j = 0; j < 4; j++) acc[mi][ni][j] = 0.f;

    for (int s = 0; s < 24; s++) {
        const int k0 = s * 32;
        uint4 rah[2], ral[2], rbh[2], rbl[2];
#pragma unroll
        for (int i = 0; i < 2; i++) {
            int idx = tid + i * 256;
            int r = idx >> 2, ce = (idx & 3) * 8;
            size_t oa = (size_t)(m0 + r) * Dx + k0 + ce;
            size_t ob = (size_t)(n0 + r) * Dx + k0 + ce;
            rah[i] = *(const uint4*)(Ah + oa);
            ral[i] = *(const uint4*)(Al + oa);
            rbh[i] = *(const uint4*)(Bh + ob);
            rbl[i] = *(const uint4*)(Bl + ob);
        }
        __syncthreads();   // prior stage's compute done reading smem
#pragma unroll
        for (int i = 0; i < 2; i++) {
            int idx = tid + i * 256;
            int r = idx >> 2;
            uint32_t off = (uint32_t)r * ROWB + (uint32_t)(idx & 3) * 16u;
            *(uint4*)(smem + SA_H + off) = rah[i];
            *(uint4*)(smem + SA_L + off) = ral[i];
            *(uint4*)(smem + SB_H + off) = rbh[i];
            *(uint4*)(smem + SB_L + off) = rbl[i];
        }
        __syncthreads();

#pragma unroll
        for (int kk = 0; kk < 2; kk++) {
            const uint32_t kB = (uint32_t)kk * 32u;
            uint32_t ah[2][4], al[2][4], bh[4][4], bl[4][4];
#pragma unroll
            for (int mi = 0; mi < 2; mi++) {
                uint32_t addr = sb + (uint32_t)(warp_m + mi * 16 + a_lrow) * ROWB
                              + kB + a_lcol;
                ldsm4(ah[mi], addr + SA_H);
                ldsm4(al[mi], addr + SA_L);
            }
#pragma unroll
            for (int p = 0; p < 4; p++) {
                uint32_t addr = sb + (uint32_t)(warp_n + p * 16 + b_nrow) * ROWB
                              + kB + b_koff;
                ldsm4(bh[p], addr + SB_H);
                ldsm4(bl[p], addr + SB_L);
            }
#pragma unroll
            for (int mi = 0; mi < 2; mi++)
#pragma unroll
                for (int p = 0; p < 4; p++) {
                    mma16816(acc[mi][2 * p],     ah[mi], bh[p]);
                    mma16816(acc[mi][2 * p + 1], ah[mi], bh[p] + 2);
                    mma16816(acc[mi][2 * p],     al[mi], bh[p]);
                    mma16816(acc[mi][2 * p + 1], al[mi], bh[p] + 2);
                    mma16816(acc[mi][2 * p],     ah[mi], bl[p]);
                    mma16816(acc[mi][2 * p + 1], ah[mi], bl[p] + 2);
                }
        }
    }

    // ---- epilogue ----
    const int lrow = lane >> 2;          // 0..7
    const int lcol = (lane & 3) * 2;     // 0,2,4,6
    if (mode == 0) {
        const int h = (n0 + warp_n) >> 6;
#pragma unroll
        for (int mi = 0; mi < 2; mi++)
#pragma unroll
            for (int half = 0; half < 2; half++) {
                int m = m0 + warp_m + mi * 16 + lrow + half * 8;
                int bb = m >> 11, t = m & (Tx - 1);
                float* base = dst + (((size_t)bb * Hx + h) * Tx + t) * HDx;
#pragma unroll
                for (int ni = 0; ni < 8; ni++) {
                    float2 v2 = { acc[mi][ni][half * 2], acc[mi][ni][half * 2 + 1] };
                    *(float2*)(base + ni * 8 + lcol) = v2;
                }
            }
    } else {
#pragma unroll
        for (int mi = 0; mi < 2; mi++)
#pragma unroll
            for (int half = 0; half < 2; half++) {
                int m = m0 + warp_m + mi * 16 + lrow + half * 8;
                float* base = dst + (size_t)m * Dx + n0 + warp_n;
#pragma unroll
                for (int ni = 0; ni < 8; ni++) {
                    int c = ni * 8 + lcol;
                    float2 v2 = { acc[mi][ni][half * 2]     + bias[n0 + warp_n + c],
                                  acc[mi][ni][half * 2 + 1] + bias[n0 + warp_n + c + 1] };
                    *(float2*)(base + c) = v2;
                }
            }
    }
}

// ---------------------------------------------------------------------------
// Causal flash attention, fp32 (unchanged).
// ---------------------------------------------------------------------------
__global__ __launch_bounds__(256) void attn64(const float* __restrict__ gq,
                                              const float* __restrict__ gk,
                                              const float* __restrict__ gv,
                                              float* __restrict__ gctx)
{
    extern __shared__ float sm[];
    float (*Qs)[65] = (float(*)[65])(sm);
    float (*Ks)[65] = (float(*)[65])(sm + 64 * 65);
    float (*Vs)[65] = (float(*)[65])(sm + 2 * 64 * 65);
    float (*Ps)[65] = (float(*)[65])(sm + 3 * 64 * 65);

    const int tid = threadIdx.x;
    const int bh  = blockIdx.y;
    const int qt  = gridDim.x - 1 - blockIdx.x;
    const int q0  = qt * 64;
    const int bb  = bh / Hx, h = bh % Hx;

    const float* qb = gq + (size_t)bh * Tx * HDx;
    const float* kb = gk + (size_t)bh * Tx * HDx;
    const float* vb = gv + (size_t)bh * Tx * HDx;

#pragma unroll
    for (int it = 0; it < 4; it++) {
        int idx = tid + it * 256;
        int r   = idx >> 4;
        int c4  = (idx & 15) << 2;
        float4 vq = *(const float4*)&qb[(size_t)(q0 + r) * HDx + c4];
        Qs[r][c4] = vq.x; Qs[r][c4 + 1] = vq.y; Qs[r][c4 + 2] = vq.z; Qs[r][c4 + 3] = vq.w;
    }

    const int trow = tid >> 4;
    const int tcol = tid & 15;
    const int r0 = trow * 4;
    const int c0 = tcol * 4;

    float o[4][4];
    float mrow[4], lrow[4];
#pragma unroll
    for (int i = 0; i < 4; i++) {
        mrow[i] = -1e30f; lrow[i] = 0.f;
#pragma unroll
        for (int j = 0; j < 4; j++) o[i][j] = 0.f;
    }

    for (int kt = 0; kt <= qt; kt++) {
        __syncthreads();
#pragma unroll
        for (int it = 0; it < 4; it++) {
            int idx = tid + it * 256;
            int r   = idx >> 4;
            int c4  = (idx & 15) << 2;
            size_t off = (size_t)(kt * 64 + r) * HDx + c4;
            float4 kv = *(const float4*)&kb[off];
            Ks[r][c4] = kv.x; Ks[r][c4 + 1] = kv.y; Ks[r][c4 + 2] = kv.z; Ks[r][c4 + 3] = kv.w;
            float4 vv = *(const float4*)&vb[off];
            Vs[r][c4] = vv.x; Vs[r][c4 + 1] = vv.y; Vs[r][c4 + 2] = vv.z; Vs[r][c4 + 3] = vv.w;
        }
        __syncthreads();

        float s[4][4];
#pragma unroll
        for (int i = 0; i < 4; i++)
#pragma unroll
            for (int j = 0; j < 4; j++) s[i][j] = 0.f;

#pragma unroll 8
        for (int d = 0; d < 64; d++) {
            float qv[4], kv[4];
#pragma unroll
            for (int i = 0; i < 4; i++) qv[i] = Qs[r0 + i][d];
#pragma unroll
            for (int j = 0; j < 4; j++) kv[j] = Ks[c0 + j][d];
#pragma unroll
            for (int i = 0; i < 4; i++)
#pragma unroll
                for (int j = 0; j < 4; j++)
                    s[i][j] += qv[i] * kv[j];
        }

#pragma unroll
        for (int i = 0; i < 4; i++)
#pragma unroll
            for (int j = 0; j < 4; j++)
                s[i][j] *= 0.125f;
        if (kt == qt) {
#pragma unroll
            for (int i = 0; i < 4; i++)
#pragma unroll
                for (int j = 0; j < 4; j++)
                    if (c0 + j > r0 + i) s[i][j] = -1e30f;
        }

#pragma unroll
        for (int i = 0; i < 4; i++) {
            float tm = fmaxf(fmaxf(s[i][0], s[i][1]), fmaxf(s[i][2], s[i][3]));
#pragma unroll
            for (int off = 8; off; off >>= 1)
                tm = fmaxf(tm, __shfl_xor_sync(0xffffffffu, tm, off));
            float mnew = fmaxf(mrow[i], tm);
            float corr = __expf(mrow[i] - mnew);
            float p[4];
            float rs = 0.f;
#pragma unroll
            for (int j = 0; j < 4; j++) { p[j] = __expf(s[i][j] - mnew); rs += p[j]; }
#pragma unroll
            for (int off = 8; off; off >>= 1)
                rs += __shfl_xor_sync(0xffffffffu, rs, off);
            lrow[i] = lrow[i] * corr + rs;
            mrow[i] = mnew;
#pragma unroll
            for (int j = 0; j < 4; j++) o[i][j] *= corr;
            Ps[r0 + i][c0 + 0] = p[0];
            Ps[r0 + i][c0 + 1] = p[1];
            Ps[r0 + i][c0 + 2] = p[2];
            Ps[r0 + i][c0 + 3] = p[3];
        }
        __syncthreads();

#pragma unroll 8
        for (int cc = 0; cc < 64; cc++) {
            float pv[4], vv[4];
#pragma unroll
            for (int i = 0; i < 4; i++) pv[i] = Ps[r0 + i][cc];
#pragma unroll
            for (int j = 0; j < 4; j++) vv[j] = Vs[cc][c0 + j];
#pragma unroll
            for (int i = 0; i < 4; i++)
#pragma unroll
                for (int j = 0; j < 4; j++)
                    o[i][j] += pv[i] * vv[j];
        }
    }

#pragma unroll
    for (int i = 0; i < 4; i++) {
        float inv = 1.0f / lrow[i];
        int tglob = q0 + r0 + i;
        float* dst = gctx + ((size_t)bb * Tx + tglob) * Dx + h * HDx + c0;
        float4 w;
        w.x = o[i][0] * inv; w.y = o[i][1] * inv;
        w.z = o[i][2] * inv; w.w = o[i][3] * inv;
        *(float4*)dst = w;
    }
}

// ---------------------------------------------------------------------------
extern "C" void kernel_launch(void* const* d_in, const int* in_sizes, int n_in,
                              void* d_out, int out_size)
{
    (void)in_sizes; (void)n_in; (void)out_size;
    const float* x  = (const float*)d_in[0];
    const float* Wq = (const float*)d_in[1];
    const float* Wk = (const float*)d_in[2];
    const float* Wv = (const float*)d_in[3];
    const float* Wo = (const float*)d_in[4];
    const float* bo = (const float*)d_in[5];
    float* out = (float*)d_out;

    float *q, *k, *v, *ctx;
    bf16 *xh, *xl, *ch, *cl, *wh, *wl;
    cudaGetSymbolAddress((void**)&q,   g_q);
    cudaGetSymbolAddress((void**)&k,   g_k);
    cudaGetSymbolAddress((void**)&v,   g_v);
    cudaGetSymbolAddress((void**)&ctx, g_ctx);
    cudaGetSymbolAddress((void**)&xh,  g_xh);
    cudaGetSymbolAddress((void**)&xl,  g_xl);
    cudaGetSymbolAddress((void**)&ch,  g_ch);
    cudaGetSymbolAddress((void**)&cl,  g_cl);
    cudaGetSymbolAddress((void**)&wh,  g_wh);
    cudaGetSymbolAddress((void**)&wl,  g_wl);

    cudaFuncSetAttribute(gemm_hmma, cudaFuncAttributeMaxDynamicSharedMemorySize, SM_GTOT);
    cudaFuncSetAttribute(attn64,    cudaFuncAttributeMaxDynamicSharedMemorySize, 4 * 64 * 65 * 4);

    const int NE = Mx * Dx;
    split_f32<<<NE / 256, 256>>>(x, xh, xl, NE);
    splitT_f32<<<WE / 256, 256>>>(Wq, wh + 0 * WE, wl + 0 * WE);
    splitT_f32<<<WE / 256, 256>>>(Wk, wh + 1 * WE, wl + 1 * WE);
    splitT_f32<<<WE / 256, 256>>>(Wv, wh + 2 * WE, wl + 2 * WE);
    splitT_f32<<<WE / 256, 256>>>(Wo, wh + 3 * WE, wl + 3 * WE);

    dim3 ggrid(Dx / 128, Mx / 128);   // (6, 64)
    gemm_hmma<<<ggrid, 256, SM_GTOT>>>(xh, xl, wh + 0 * WE, wl + 0 * WE, q, nullptr, 0);
    gemm_hmma<<<ggrid, 256, SM_GTOT>>>(xh, xl, wh + 1 * WE, wl + 1 * WE, k, nullptr, 0);
    gemm_hmma<<<ggrid, 256, SM_GTOT>>>(xh, xl, wh + 2 * WE, wl + 2 * WE, v, nullptr, 0);

    const int asmem = 4 * 64 * 65 * 4;
    attn64<<<dim3(Tx / 64, Bx * Hx), 256, asmem>>>(q, k, v, ctx);

    split_f32<<<NE / 256, 256>>>(ctx, ch, cl, NE);
    gemm_hmma<<<ggrid, 256, SM_GTOT>>>(ch, cl, wh + 3 * WE, wl + 3 * WE, out, bo, 1);
}

// round 8
// speedup vs baseline: 2.8188x; 1.9562x over previous
#include <cuda_runtime.h>
#include <cuda_bf16.h>
#include <math.h>
#include <stdint.h>

#define Bx  4
#define Tx  2048
#define Dx  768
#define Hx  12
#define HDx 64
#define Mx  (Bx*Tx)   // 8192
#define WE  (Dx*Dx)   // 589824

typedef __nv_bfloat16 bf16;

// ---------------- scratch (allocation-free rule: __device__ globals) -------
__device__ bf16 g_xh[Mx*Dx], g_xl[Mx*Dx];
__device__ bf16 g_ch[Mx*Dx], g_cl[Mx*Dx];
__device__ bf16 g_wh[4*WE],  g_wl[4*WE];     // K-major [N][K] weights
__device__ bf16 g_qh[Bx*Hx*Tx*HDx], g_ql[Bx*Hx*Tx*HDx];   // [b,h,t,hd]
__device__ bf16 g_kh[Bx*Hx*Tx*HDx], g_kl[Bx*Hx*Tx*HDx];   // [b,h,t,hd]
__device__ bf16 g_vth[Bx*Hx*HDx*Tx], g_vtl[Bx*Hx*HDx*Tx]; // [b,h,hd,t]

// ---------------- portable tensor-core helpers (sm_80+) --------------------
__device__ __forceinline__ uint32_t smem_u32(const void* p) {
    uint32_t a;
    asm("{ .reg .u64 t; cvta.to.shared.u64 t, %1; cvt.u32.u64 %0, t; }"
        : "=r"(a) : "l"(p));
    return a;
}
__device__ __forceinline__ void ldsm4(uint32_t* r, uint32_t addr) {
    asm volatile("ldmatrix.sync.aligned.m8n8.x4.shared.b16 {%0,%1,%2,%3}, [%4];"
                 : "=r"(r[0]), "=r"(r[1]), "=r"(r[2]), "=r"(r[3]) : "r"(addr));
}
__device__ __forceinline__ void mma16816(float* c, const uint32_t* a, const uint32_t* b) {
    asm volatile("mma.sync.aligned.m16n8k16.row.col.f32.bf16.bf16.f32 "
                 "{%0,%1,%2,%3}, {%4,%5,%6,%7}, {%8,%9}, {%0,%1,%2,%3};"
                 : "+f"(c[0]), "+f"(c[1]), "+f"(c[2]), "+f"(c[3])
                 : "r"(a[0]), "r"(a[1]), "r"(a[2]), "r"(a[3]),
                   "r"(b[0]), "r"(b[1]));
}
__device__ __forceinline__ void cp16(uint32_t s, const void* g) {
    asm volatile("cp.async.cg.shared.global [%0], [%1], 16;" :: "r"(s), "l"(g));
}
__device__ __forceinline__ void cp_commit() {
    asm volatile("cp.async.commit_group;" ::: "memory");
}
template<int N> __device__ __forceinline__ void cp_wait() {
    asm volatile("cp.async.wait_group %0;" :: "n"(N) : "memory");
}
__device__ __forceinline__ uint32_t pack2(bf16 a, bf16 b) {
    __nv_bfloat162 t(a, b);
    return *reinterpret_cast<uint32_t*>(&t);
}

// ---------------------------------------------------------------------------
// Split-precision conversion kernels
// ---------------------------------------------------------------------------
__global__ void split_f32(const float* __restrict__ in,
                          bf16* __restrict__ hi, bf16* __restrict__ lo, int n) {
    int i = blockIdx.x * 256 + threadIdx.x;
    if (i < n) {
        float f = in[i];
        bf16 h = __float2bfloat16(f);
        hi[i] = h;
        lo[i] = __float2bfloat16(f - __bfloat162float(h));
    }
}
__global__ void splitT_f32(const float* __restrict__ w,
                           bf16* __restrict__ hi, bf16* __restrict__ lo) {
    int i = blockIdx.x * 256 + threadIdx.x;   // i = n*Dx + k
    int n = i / Dx, k = i - n * Dx;
    float f = w[(size_t)k * Dx + n];
    bf16 h = __float2bfloat16(f);
    hi[i] = h;
    lo[i] = __float2bfloat16(f - __bfloat162float(h));
}

// ---------------------------------------------------------------------------
// HMMA bf16x3 GEMM: C[M,768] = A[M,768] @ B^T  (B stored [N,K] K-major)
// mode 0: bf16 hi/lo -> [b,h,t,hd]   (Q, K)
// mode 2: bf16 hi/lo -> [b,h,hd,t]   (V transposed)
// mode 1: fp32 + bias row-major       (output proj)
// ---------------------------------------------------------------------------
#define PAD_ELEM 40
#define ROWB     (PAD_ELEM*2)        // 80 bytes
#define TILE_B   (128*ROWB)
#define SA_H 0
#define SA_L (TILE_B)
#define SB_H (2*TILE_B)
#define SB_L (3*TILE_B)
#define SM_GTOT (4*TILE_B)

__global__ __launch_bounds__(256) void gemm_hmma(
    const bf16* __restrict__ Ah, const bf16* __restrict__ Al,
    const bf16* __restrict__ Bh, const bf16* __restrict__ Bl,
    float* __restrict__ dst, bf16* __restrict__ dsth, bf16* __restrict__ dstl,
    const float* __restrict__ bias, int mode)
{
    extern __shared__ char smem[];
    const uint32_t sb = smem_u32(smem);
    const int tid = threadIdx.x, wid = tid >> 5, lane = tid & 31;
    const int m0 = blockIdx.y * 128, n0 = blockIdx.x * 128;

    const int warp_m = (wid & 3) * 32;
    const int warp_n = (wid >> 2) * 64;

    const uint32_t a_lrow = (uint32_t)(lane & 15);
    const uint32_t a_lcol = (uint32_t)(lane >> 4) * 16u;
    const uint32_t b_l = (uint32_t)(lane & 7), b_g = (uint32_t)(lane >> 3);
    const uint32_t b_nrow = ((b_g >> 1) << 3) + b_l;
    const uint32_t b_koff = (b_g & 1) << 4;

    float acc[2][8][4];
#pragma unroll
    for (int mi = 0; mi < 2; mi++)
#pragma unroll
        for (int ni = 0; ni < 8; ni++)
#pragma unroll
            for (int j = 0; j < 4; j++) acc[mi][ni][j] = 0.f;

    for (int s = 0; s < 24; s++) {
        const int k0 = s * 32;
        uint4 rah[2], ral[2], rbh[2], rbl[2];
#pragma unroll
        for (int i = 0; i < 2; i++) {
            int idx = tid + i * 256;
            int r = idx >> 2, ce = (idx & 3) * 8;
            size_t oa = (size_t)(m0 + r) * Dx + k0 + ce;
            size_t ob = (size_t)(n0 + r) * Dx + k0 + ce;
            rah[i] = *(const uint4*)(Ah + oa);
            ral[i] = *(const uint4*)(Al + oa);
            rbh[i] = *(const uint4*)(Bh + ob);
            rbl[i] = *(const uint4*)(Bl + ob);
        }
        __syncthreads();
#pragma unroll
        for (int i = 0; i < 2; i++) {
            int idx = tid + i * 256;
            int r = idx >> 2;
            uint32_t off = (uint32_t)r * ROWB + (uint32_t)(idx & 3) * 16u;
            *(uint4*)(smem + SA_H + off) = rah[i];
            *(uint4*)(smem + SA_L + off) = ral[i];
            *(uint4*)(smem + SB_H + off) = rbh[i];
            *(uint4*)(smem + SB_L + off) = rbl[i];
        }
        __syncthreads();

#pragma unroll
        for (int kk = 0; kk < 2; kk++) {
            const uint32_t kB = (uint32_t)kk * 32u;
            uint32_t ah[2][4], al[2][4], bh[4][4], bl[4][4];
#pragma unroll
            for (int mi = 0; mi < 2; mi++) {
                uint32_t addr = sb + (uint32_t)(warp_m + mi * 16 + a_lrow) * ROWB
                              + kB + a_lcol;
                ldsm4(ah[mi], addr + SA_H);
                ldsm4(al[mi], addr + SA_L);
            }
#pragma unroll
            for (int p = 0; p < 4; p++) {
                uint32_t addr = sb + (uint32_t)(warp_n + p * 16 + b_nrow) * ROWB
                              + kB + b_koff;
                ldsm4(bh[p], addr + SB_H);
                ldsm4(bl[p], addr + SB_L);
            }
#pragma unroll
            for (int mi = 0; mi < 2; mi++)
#pragma unroll
                for (int p = 0; p < 4; p++) {
                    mma16816(acc[mi][2 * p],     ah[mi], bh[p]);
                    mma16816(acc[mi][2 * p + 1], ah[mi], bh[p] + 2);
                    mma16816(acc[mi][2 * p],     al[mi], bh[p]);
                    mma16816(acc[mi][2 * p + 1], al[mi], bh[p] + 2);
                    mma16816(acc[mi][2 * p],     ah[mi], bl[p]);
                    mma16816(acc[mi][2 * p + 1], ah[mi], bl[p] + 2);
                }
        }
    }

    const int lrow = lane >> 2;
    const int lcol = (lane & 3) * 2;
    if (mode == 0) {
        const int h = (n0 + warp_n) >> 6;
#pragma unroll
        for (int mi = 0; mi < 2; mi++)
#pragma unroll
            for (int half = 0; half < 2; half++) {
                int m = m0 + warp_m + mi * 16 + lrow + half * 8;
                int bb = m >> 11, t = m & (Tx - 1);
                size_t base = (((size_t)bb * Hx + h) * Tx + t) * HDx;
#pragma unroll
                for (int ni = 0; ni < 8; ni++) {
                    float v0 = acc[mi][ni][half * 2], v1 = acc[mi][ni][half * 2 + 1];
                    bf16 h0 = __float2bfloat16(v0), h1 = __float2bfloat16(v1);
                    bf16 l0 = __float2bfloat16(v0 - __bfloat162float(h0));
                    bf16 l1 = __float2bfloat16(v1 - __bfloat162float(h1));
                    size_t a = base + ni * 8 + lcol;
                    *(uint32_t*)(dsth + a) = pack2(h0, h1);
                    *(uint32_t*)(dstl + a) = pack2(l0, l1);
                }
            }
    } else if (mode == 2) {
        const int h = (n0 + warp_n) >> 6;
#pragma unroll
        for (int mi = 0; mi < 2; mi++)
#pragma unroll
            for (int half = 0; half < 2; half++) {
                int m = m0 + warp_m + mi * 16 + lrow + half * 8;
                int bb = m >> 11, t = m & (Tx - 1);
                size_t hb = ((size_t)bb * Hx + h) * HDx;
#pragma unroll
                for (int ni = 0; ni < 8; ni++)
#pragma unroll
                    for (int c = 0; c < 2; c++) {
                        int hd = ni * 8 + lcol + c;
                        float v = acc[mi][ni][half * 2 + c];
                        bf16 hv = __float2bfloat16(v);
                        bf16 lv = __float2bfloat16(v - __bfloat162float(hv));
                        size_t a = (hb + hd) * Tx + t;
                        dsth[a] = hv;
                        dstl[a] = lv;
                    }
            }
    } else {
#pragma unroll
        for (int mi = 0; mi < 2; mi++)
#pragma unroll
            for (int half = 0; half < 2; half++) {
                int m = m0 + warp_m + mi * 16 + lrow + half * 8;
                float* base = dst + (size_t)m * Dx + n0 + warp_n;
#pragma unroll
                for (int ni = 0; ni < 8; ni++) {
                    int c = ni * 8 + lcol;
                    float2 v2 = { acc[mi][ni][half * 2]     + bias[n0 + warp_n + c],
                                  acc[mi][ni][half * 2 + 1] + bias[n0 + warp_n + c + 1] };
                    *(float2*)(base + c) = v2;
                }
            }
    }
}

// ---------------------------------------------------------------------------
// HMMA causal flash attention (bf16x3 split precision).
// 128 threads, q-tile 64 (16 rows/warp), kv-tile 64, cp.async double buffer.
// Reads qh/ql,kh/kl [b,h,t,hd] and vth/vtl [b,h,hd,t]; writes ctx bf16 hi/lo.
// ---------------------------------------------------------------------------
#define AT_STRIDE 144                   // 128 + 16 byte row stride
#define AQ_H 0
#define AQ_L 9216
#define AKV0 18432
#define AKV_STG 36864                   // Kh,Kl,Vh,Vl @ 0,9216,18432,27648
#define ASM_TOT (AKV0 + 2*AKV_STG)      // 92160

__global__ __launch_bounds__(128) void attn_hmma(
    const bf16* __restrict__ qh, const bf16* __restrict__ ql,
    const bf16* __restrict__ kh, const bf16* __restrict__ kl,
    const bf16* __restrict__ vth, const bf16* __restrict__ vtl,
    bf16* __restrict__ ch, bf16* __restrict__ cl)
{
    extern __shared__ char smem[];
    const uint32_t sb = smem_u32(smem);
    const int tid = threadIdx.x, wid = tid >> 5, lane = tid & 31;
    const int bh = blockIdx.y;
    const int qt = gridDim.x - 1 - blockIdx.x;     // big tiles first
    const int q0 = qt * 64;
    const int bb = bh / Hx, h = bh - bb * Hx;

    const bf16* qhb = qh + (size_t)bh * Tx * HDx;
    const bf16* qlb = ql + (size_t)bh * Tx * HDx;
    const bf16* khb = kh + (size_t)bh * Tx * HDx;
    const bf16* klb = kl + (size_t)bh * Tx * HDx;
    const bf16* vhb = vth + (size_t)bh * HDx * Tx;
    const bf16* vlb = vtl + (size_t)bh * HDx * Tx;

    // ---- Q tile loads (cp.async group) ----
#pragma unroll
    for (int i = 0; i < 4; i++) {
        int idx = tid + i * 128;
        int r = idx >> 3, c8 = idx & 7;
        uint32_t so = (uint32_t)r * AT_STRIDE + (uint32_t)c8 * 16u;
        size_t go = (size_t)(q0 + r) * HDx + c8 * 8;
        cp16(sb + AQ_H + so, qhb + go);
        cp16(sb + AQ_L + so, qlb + go);
    }
    cp_commit();

    // ---- KV stage loader ----
    auto load_kv = [&](int kt, int stage) {
        uint32_t base = sb + AKV0 + (uint32_t)stage * AKV_STG;
#pragma unroll
        for (int i = 0; i < 4; i++) {
            int idx = tid + i * 128;
            int r = idx >> 3, c8 = idx & 7;
            uint32_t so = (uint32_t)r * AT_STRIDE + (uint32_t)c8 * 16u;
            size_t gk = (size_t)(kt * 64 + r) * HDx + c8 * 8;
            cp16(base +     0 + so, khb + gk);
            cp16(base +  9216 + so, klb + gk);
            size_t gv = (size_t)r * Tx + kt * 64 + c8 * 8;
            cp16(base + 18432 + so, vhb + gv);
            cp16(base + 27648 + so, vlb + gv);
        }
    };
    load_kv(0, 0);
    cp_commit();

    cp_wait<1>();            // Q group done
    __syncthreads();

    // ---- Q A-fragments, held in registers for the whole CTA ----
    const uint32_t a_lrow = (uint32_t)(lane & 15);
    const uint32_t a_lcol = (uint32_t)(lane >> 4) * 16u;
    uint32_t qfh[4][4], qfl[4][4];
#pragma unroll
    for (int ks = 0; ks < 4; ks++) {
        uint32_t addr = sb + (uint32_t)(wid * 16 + a_lrow) * AT_STRIDE
                      + (uint32_t)ks * 32u + a_lcol;
        ldsm4(qfh[ks], addr + AQ_H);
        ldsm4(qfl[ks], addr + AQ_L);
    }

    const uint32_t b_l = (uint32_t)(lane & 7), b_g = (uint32_t)(lane >> 3);
    const uint32_t b_nrow = ((b_g >> 1) << 3) + b_l;
    const uint32_t b_koff = (b_g & 1) << 4;

    float o[8][4];
#pragma unroll
    for (int ni = 0; ni < 8; ni++)
#pragma unroll
        for (int j = 0; j < 4; j++) o[ni][j] = 0.f;
    float mrow[2] = { -1e30f, -1e30f };
    float lrow[2] = { 0.f, 0.f };

    const int rl = lane >> 2;            // local row 0..7
    const int cl2 = (lane & 3) * 2;      // local col pair base

    for (int kt = 0; kt <= qt; kt++) {
        const int cur = kt & 1;
        if (kt < qt) { load_kv(kt + 1, cur ^ 1); cp_commit(); cp_wait<1>(); }
        else         { cp_wait<0>(); }
        __syncthreads();

        const uint32_t kbase = sb + AKV0 + (uint32_t)cur * AKV_STG;

        // ---- S = Q K^T (bf16x3) ----
        float s[8][4];
#pragma unroll
        for (int ni = 0; ni < 8; ni++)
#pragma unroll
            for (int j = 0; j < 4; j++) s[ni][j] = 0.f;

#pragma unroll
        for (int ks = 0; ks < 4; ks++) {
            uint32_t kfh[4][4], kfl[4][4];
#pragma unroll
            for (int p = 0; p < 4; p++) {
                uint32_t addr = kbase + (uint32_t)(p * 16 + b_nrow) * AT_STRIDE
                              + (uint32_t)ks * 32u + b_koff;
                ldsm4(kfh[p], addr);
                ldsm4(kfl[p], addr + 9216);
            }
#pragma unroll
            for (int p = 0; p < 4; p++) {
                mma16816(s[2 * p],     qfh[ks], kfh[p]);
                mma16816(s[2 * p + 1], qfh[ks], kfh[p] + 2);
                mma16816(s[2 * p],     qfl[ks], kfh[p]);
                mma16816(s[2 * p + 1], qfl[ks], kfh[p] + 2);
                mma16816(s[2 * p],     qfh[ks], kfl[p]);
                mma16816(s[2 * p + 1], qfh[ks], kfl[p] + 2);
            }
        }

        // ---- scale + causal mask ----
#pragma unroll
        for (int ni = 0; ni < 8; ni++)
#pragma unroll
            for (int j = 0; j < 4; j++) s[ni][j] *= 0.125f;
        if (kt == qt) {
            int r0loc = wid * 16 + rl;
#pragma unroll
            for (int ni = 0; ni < 8; ni++) {
                int c = ni * 8 + cl2;
                if (c     > r0loc)     s[ni][0] = -1e30f;
                if (c + 1 > r0loc)     s[ni][1] = -1e30f;
                if (c     > r0loc + 8) s[ni][2] = -1e30f;
                if (c + 1 > r0loc + 8) s[ni][3] = -1e30f;
            }
        }

        // ---- online softmax (2 rows per thread) ----
#pragma unroll
        for (int half = 0; half < 2; half++) {
            float tm = -1e30f;
#pragma unroll
            for (int ni = 0; ni < 8; ni++)
                tm = fmaxf(tm, fmaxf(s[ni][half * 2], s[ni][half * 2 + 1]));
            tm = fmaxf(tm, __shfl_xor_sync(0xffffffffu, tm, 1));
            tm = fmaxf(tm, __shfl_xor_sync(0xffffffffu, tm, 2));
            float mnew = fmaxf(mrow[half], tm);
            float corr = __expf(mrow[half] - mnew);
            float rs = 0.f;
#pragma unroll
            for (int ni = 0; ni < 8; ni++) {
                float p0 = __expf(s[ni][half * 2]     - mnew);
                float p1 = __expf(s[ni][half * 2 + 1] - mnew);
                s[ni][half * 2] = p0; s[ni][half * 2 + 1] = p1;
                rs += p0 + p1;
            }
            rs += __shfl_xor_sync(0xffffffffu, rs, 1);
            rs += __shfl_xor_sync(0xffffffffu, rs, 2);
            lrow[half] = lrow[half] * corr + rs;
            mrow[half] = mnew;
#pragma unroll
            for (int ni = 0; ni < 8; ni++) {
                o[ni][half * 2] *= corr; o[ni][half * 2 + 1] *= corr;
            }
        }

        // ---- O += P V (bf16x3, P from registers) ----
#pragma unroll
        for (int ks = 0; ks < 4; ks++) {
            uint32_t pah[4], pal[4];
#pragma unroll
            for (int g = 0; g < 2; g++) {      // g: k-halves (frags 2ks, 2ks+1)
                int ni = 2 * ks + g;
#pragma unroll
                for (int hf = 0; hf < 2; hf++) {
                    float v0 = s[ni][hf * 2], v1 = s[ni][hf * 2 + 1];
                    bf16 h0 = __float2bfloat16(v0), h1 = __float2bfloat16(v1);
                    bf16 l0 = __float2bfloat16(v0 - __bfloat162float(h0));
                    bf16 l1 = __float2bfloat16(v1 - __bfloat162float(h1));
                    pah[g * 2 + hf] = pack2(h0, h1);
                    pal[g * 2 + hf] = pack2(l0, l1);
                }
            }
            // reorder: mma A wants {(r,k0-7),(r+8,k0-7),(r,k8-15),(r+8,k8-15)}
            uint32_t ah[4] = { pah[0], pah[1], pah[2], pah[3] };
            uint32_t al[4] = { pal[0], pal[1], pal[2], pal[3] };
#pragma unroll
            for (int p = 0; p < 4; p++) {
                uint32_t vfh[4], vfl[4];
                uint32_t addr = kbase + 18432
                              + (uint32_t)(p * 16 + b_nrow) * AT_STRIDE
                              + (uint32_t)ks * 32u + b_koff;
                ldsm4(vfh, addr);
                ldsm4(vfl, addr + 9216);
                mma16816(o[2 * p],     ah, vfh);
                mma16816(o[2 * p + 1], ah, vfh + 2);
                mma16816(o[2 * p],     al, vfh);
                mma16816(o[2 * p + 1], al, vfh + 2);
                mma16816(o[2 * p],     ah, vfl);
                mma16816(o[2 * p + 1], ah, vfl + 2);
            }
        }
        __syncthreads();   // all warps done with this stage before it is refilled
    }

    // ---- epilogue: normalize, split to bf16 hi/lo ctx [b,t,D] ----
#pragma unroll
    for (int half = 0; half < 2; half++) {
        int r = q0 + wid * 16 + rl + half * 8;
        float inv = 1.0f / lrow[half];
        size_t base = ((size_t)bb * Tx + r) * Dx + h * HDx + cl2;
#pragma unroll
        for (int ni = 0; ni < 8; ni++) {
            float v0 = o[ni][half * 2] * inv, v1 = o[ni][half * 2 + 1] * inv;
            bf16 h0 = __float2bfloat16(v0), h1 = __float2bfloat16(v1);
            bf16 l0 = __float2bfloat16(v0 - __bfloat162float(h0));
            bf16 l1 = __float2bfloat16(v1 - __bfloat162float(h1));
            *(uint32_t*)(ch + base + ni * 8) = pack2(h0, h1);
            *(uint32_t*)(cl + base + ni * 8) = pack2(l0, l1);
        }
    }
}

// ---------------------------------------------------------------------------
extern "C" void kernel_launch(void* const* d_in, const int* in_sizes, int n_in,
                              void* d_out, int out_size)
{
    (void)in_sizes; (void)n_in; (void)out_size;
    const float* x  = (const float*)d_in[0];
    const float* Wq = (const float*)d_in[1];
    const float* Wk = (const float*)d_in[2];
    const float* Wv = (const float*)d_in[3];
    const float* Wo = (const float*)d_in[4];
    const float* bo = (const float*)d_in[5];
    float* out = (float*)d_out;

    bf16 *xh, *xl, *ch, *cl, *wh, *wl, *qh, *ql, *kh, *kl, *vth, *vtl;
    cudaGetSymbolAddress((void**)&xh,  g_xh);
    cudaGetSymbolAddress((void**)&xl,  g_xl);
    cudaGetSymbolAddress((void**)&ch,  g_ch);
    cudaGetSymbolAddress((void**)&cl,  g_cl);
    cudaGetSymbolAddress((void**)&wh,  g_wh);
    cudaGetSymbolAddress((void**)&wl,  g_wl);
    cudaGetSymbolAddress((void**)&qh,  g_qh);
    cudaGetSymbolAddress((void**)&ql,  g_ql);
    cudaGetSymbolAddress((void**)&kh,  g_kh);
    cudaGetSymbolAddress((void**)&kl,  g_kl);
    cudaGetSymbolAddress((void**)&vth, g_vth);
    cudaGetSymbolAddress((void**)&vtl, g_vtl);

    cudaFuncSetAttribute(gemm_hmma, cudaFuncAttributeMaxDynamicSharedMemorySize, SM_GTOT);
    cudaFuncSetAttribute(attn_hmma, cudaFuncAttributeMaxDynamicSharedMemorySize, ASM_TOT);

    const int NE = Mx * Dx;
    split_f32<<<NE / 256, 256>>>(x, xh, xl, NE);
    splitT_f32<<<WE / 256, 256>>>(Wq, wh + 0 * WE, wl + 0 * WE);
    splitT_f32<<<WE / 256, 256>>>(Wk, wh + 1 * WE, wl + 1 * WE);
    splitT_f32<<<WE / 256, 256>>>(Wv, wh + 2 * WE, wl + 2 * WE);
    splitT_f32<<<WE / 256, 256>>>(Wo, wh + 3 * WE, wl + 3 * WE);

    dim3 ggrid(Dx / 128, Mx / 128);   // (6, 64)
    gemm_hmma<<<ggrid, 256, SM_GTOT>>>(xh, xl, wh + 0 * WE, wl + 0 * WE,
                                       nullptr, qh, ql, nullptr, 0);
    gemm_hmma<<<ggrid, 256, SM_GTOT>>>(xh, xl, wh + 1 * WE, wl + 1 * WE,
                                       nullptr, kh, kl, nullptr, 0);
    gemm_hmma<<<ggrid, 256, SM_GTOT>>>(xh, xl, wh + 2 * WE, wl + 2 * WE,
                                       nullptr, vth, vtl, nullptr, 2);

    attn_hmma<<<dim3(Tx / 64, Bx * Hx), 128, ASM_TOT>>>(qh, ql, kh, kl, vth, vtl, ch, cl);

    gemm_hmma<<<ggrid, 256, SM_GTOT>>>(ch, cl, wh + 3 * WE, wl + 3 * WE,
                                       out, nullptr, nullptr, bo, 1);
}